// round 1
// baseline (speedup 1.0000x reference)
#include <cuda_runtime.h>
#include <cstddef>

// Mip chain: [6, 2048, 2048, 3] f32 -> 2x2 avg pool repeatedly down to 16.
// Output = concat(base, mip1..mip7) in element order.

#define FACES 6
#define R0 2048

// element offsets of each level in the output buffer
#define OFF0 0ull
#define OFF1 75497472ull    // + 6*2048*2048*3
#define OFF2 94371840ull    // + 6*1024*1024*3
#define OFF3 99090432ull    // + 6*512*512*3
#define OFF4 100270080ull   // + 6*256*256*3
#define OFF5 100564992ull   // + 6*128*128*3
#define OFF6 100638720ull   // + 6*64*64*3
#define OFF7 100657152ull   // + 6*32*32*3

// Kernel 1: per block = 32x32 base tile of one face.
//   - copies base tile to out level 0 (so base is read exactly once)
//   - produces mip1 (16x16), mip2 (8x8), mip3 (4x4), mip4 (2x2), mip5 (1x1) for that tile
__global__ __launch_bounds__(256) void mip_stage1(const float* __restrict__ base,
                                                  float* __restrict__ out) {
    const int f  = blockIdx.z;
    const int tX = blockIdx.x;   // 0..63
    const int tY = blockIdx.y;   // 0..63
    const int t  = threadIdx.x;  // 0..255

    const int qy = t >> 4;       // 0..15  quad row within tile
    const int qx = t & 15;       // 0..15  quad col within tile
    const int by = tY * 32 + qy * 2;
    const int bx = tX * 32 + qx * 2;

    __shared__ float s1[16 * 16 * 3];
    __shared__ float s2[8 * 8 * 3];
    __shared__ float s3[4 * 4 * 3];
    __shared__ float s4[2 * 2 * 3];

    // ---- load 2x2 quad (channels-last, 6 floats per row, 8B-aligned) ----
    const size_t row0 = ((size_t)(f * R0 + by) * R0 + bx) * 3;
    const size_t row1 = ((size_t)(f * R0 + by + 1) * R0 + bx) * 3;

    const float2* r0 = reinterpret_cast<const float2*>(base + row0);
    const float2* r1 = reinterpret_cast<const float2*>(base + row1);
    float2 a0 = r0[0], a1 = r0[1], a2 = r0[2];
    float2 b0 = r1[0], b1 = r1[1], b2 = r1[2];

    // ---- identity copy of base into level 0 ----
    float2* w0 = reinterpret_cast<float2*>(out + row0);
    float2* w1 = reinterpret_cast<float2*>(out + row1);
    w0[0] = a0; w0[1] = a1; w0[2] = a2;
    w1[0] = b0; w1[1] = b1; w1[2] = b2;

    // ---- mip1 pixel: channel-wise average of the quad ----
    // row layout: [p0.r p0.g][p0.b p1.r][p1.g p1.b]
    float cr = (a0.x + a1.y + b0.x + b1.y) * 0.25f;
    float cg = (a0.y + a2.x + b0.y + b2.x) * 0.25f;
    float cb = (a1.x + a2.y + b1.x + b2.y) * 0.25f;

    {
        const int y1 = tY * 16 + qy, x1 = tX * 16 + qx;
        const size_t o = OFF1 + ((size_t)(f * 1024 + y1) * 1024 + x1) * 3;
        out[o] = cr; out[o + 1] = cg; out[o + 2] = cb;
        const int si = (qy * 16 + qx) * 3;
        s1[si] = cr; s1[si + 1] = cg; s1[si + 2] = cb;
    }
    __syncthreads();

    // ---- mip2: 8x8 (64 threads) ----
    if (t < 64) {
        const int ly = t >> 3, lx = t & 7;
        float vr = 0.f, vg = 0.f, vb = 0.f;
        #pragma unroll
        for (int dy = 0; dy < 2; dy++)
            #pragma unroll
            for (int dx = 0; dx < 2; dx++) {
                const int i = ((ly * 2 + dy) * 16 + (lx * 2 + dx)) * 3;
                vr += s1[i]; vg += s1[i + 1]; vb += s1[i + 2];
            }
        vr *= 0.25f; vg *= 0.25f; vb *= 0.25f;
        const size_t o = OFF2 + ((size_t)(f * 512 + tY * 8 + ly) * 512 + tX * 8 + lx) * 3;
        out[o] = vr; out[o + 1] = vg; out[o + 2] = vb;
        const int si = (ly * 8 + lx) * 3;
        s2[si] = vr; s2[si + 1] = vg; s2[si + 2] = vb;
    }
    __syncthreads();

    // ---- mip3: 4x4 (16 threads) ----
    if (t < 16) {
        const int ly = t >> 2, lx = t & 3;
        float vr = 0.f, vg = 0.f, vb = 0.f;
        #pragma unroll
        for (int dy = 0; dy < 2; dy++)
            #pragma unroll
            for (int dx = 0; dx < 2; dx++) {
                const int i = ((ly * 2 + dy) * 8 + (lx * 2 + dx)) * 3;
                vr += s2[i]; vg += s2[i + 1]; vb += s2[i + 2];
            }
        vr *= 0.25f; vg *= 0.25f; vb *= 0.25f;
        const size_t o = OFF3 + ((size_t)(f * 256 + tY * 4 + ly) * 256 + tX * 4 + lx) * 3;
        out[o] = vr; out[o + 1] = vg; out[o + 2] = vb;
        const int si = (ly * 4 + lx) * 3;
        s3[si] = vr; s3[si + 1] = vg; s3[si + 2] = vb;
    }
    __syncthreads();

    // ---- mip4: 2x2 (4 threads) ----
    if (t < 4) {
        const int ly = t >> 1, lx = t & 1;
        float vr = 0.f, vg = 0.f, vb = 0.f;
        #pragma unroll
        for (int dy = 0; dy < 2; dy++)
            #pragma unroll
            for (int dx = 0; dx < 2; dx++) {
                const int i = ((ly * 2 + dy) * 4 + (lx * 2 + dx)) * 3;
                vr += s3[i]; vg += s3[i + 1]; vb += s3[i + 2];
            }
        vr *= 0.25f; vg *= 0.25f; vb *= 0.25f;
        const size_t o = OFF4 + ((size_t)(f * 128 + tY * 2 + ly) * 128 + tX * 2 + lx) * 3;
        out[o] = vr; out[o + 1] = vg; out[o + 2] = vb;
        const int si = (ly * 2 + lx) * 3;
        s4[si] = vr; s4[si + 1] = vg; s4[si + 2] = vb;
    }
    __syncthreads();

    // ---- mip5: 1 pixel per block ----
    if (t == 0) {
        #pragma unroll
        for (int c = 0; c < 3; c++) {
            float v = (s4[0 + c] + s4[3 + c] + s4[6 + c] + s4[9 + c]) * 0.25f;
            out[OFF5 + ((size_t)(f * 64 + tY) * 64 + tX) * 3 + c] = v;
        }
    }
}

// Kernel 2: mip5 (64x64) -> mip6 (32x32) -> mip7 (16x16), one block per face.
__global__ __launch_bounds__(256) void mip_stage2(float* __restrict__ out) {
    const int f = blockIdx.x;
    const int t = threadIdx.x;  // 0..255

    __shared__ float s6[32 * 32 * 3];

    const float* m5 = out + OFF5 + (size_t)f * 64 * 64 * 3;
    float* m6 = out + OFF6 + (size_t)f * 32 * 32 * 3;
    float* m7 = out + OFF7 + (size_t)f * 16 * 16 * 3;

    // mip6: 1024 pixels, 4 per thread
    for (int p = t; p < 32 * 32; p += 256) {
        const int y = p >> 5, x = p & 31;
        #pragma unroll
        for (int c = 0; c < 3; c++) {
            float v = (m5[((2 * y) * 64 + 2 * x) * 3 + c] +
                       m5[((2 * y) * 64 + 2 * x + 1) * 3 + c] +
                       m5[((2 * y + 1) * 64 + 2 * x) * 3 + c] +
                       m5[((2 * y + 1) * 64 + 2 * x + 1) * 3 + c]) * 0.25f;
            m6[p * 3 + c] = v;
            s6[p * 3 + c] = v;
        }
    }
    __syncthreads();

    // mip7: 256 pixels, 1 per thread
    {
        const int y = t >> 4, x = t & 15;
        #pragma unroll
        for (int c = 0; c < 3; c++) {
            float v = (s6[((2 * y) * 32 + 2 * x) * 3 + c] +
                       s6[((2 * y) * 32 + 2 * x + 1) * 3 + c] +
                       s6[((2 * y + 1) * 32 + 2 * x) * 3 + c] +
                       s6[((2 * y + 1) * 32 + 2 * x + 1) * 3 + c]) * 0.25f;
            m7[t * 3 + c] = v;
        }
    }
}

extern "C" void kernel_launch(void* const* d_in, const int* in_sizes, int n_in,
                              void* d_out, int out_size) {
    const float* base = (const float*)d_in[0];
    float* out = (float*)d_out;

    dim3 g1(64, 64, 6);
    mip_stage1<<<g1, 256>>>(base, out);
    mip_stage2<<<6, 256>>>(out);
}